// round 9
// baseline (speedup 1.0000x reference)
#include <cuda_runtime.h>
#include <cuda_fp16.h>
#include <math.h>

#define NN 50000
#define NE 800000
#define IN_C 128
#define HID 32
#define HEADS 8
#define H1C (HEADS*HID)   // 256
#define OUT_C 64
#define NEG_SLOPE 0.2f
#define EPS_F 1e-16f
#define SCAN_B 1024

__device__ __half g_h1h[(size_t)NN * H1C];
__device__ float  g_out1[(size_t)NN * H1C];
__device__ __half g_h2h[(size_t)NN * OUT_C];
__device__ float g_asrc1[NN * HEADS];
__device__ float g_adst1[NN * HEADS];
__device__ float g_asrc2[NN];
__device__ float g_adst2[NN];
// CSR (by dst). After scatter, g_off[d] = segment END (start = end - deg).
__device__ int g_deg[NN];
__device__ int g_off[NN];
__device__ int g_esrc[NE];
__device__ int g_bsum[(NN + SCAN_B - 1) / SCAN_B];
__device__ int g_boff[(NN + SCAN_B - 1) / SCAN_B];

__device__ __forceinline__ float lrelu(float x) { return x >= 0.0f ? x : NEG_SLOPE * x; }
__device__ __forceinline__ unsigned f2tf32(float f) {
    unsigned u;
    asm("cvt.rna.tf32.f32 %0, %1;" : "=r"(u) : "f"(f));
    return u;
}

__global__ void ifill_kernel(int* __restrict__ p, int n, int v) {
    int i = blockIdx.x * blockDim.x + threadIdx.x;
    if (i < n) p[i] = v;
}

// ---------------- CSR build ----------------
__global__ void hist_kernel(const int* __restrict__ ei, int E) {
    int e = blockIdx.x * blockDim.x + threadIdx.x;
    if (e >= E) return;
    atomicAdd(&g_deg[ei[E + e]], 1);
}

__global__ void scan1_kernel(int n) {
    __shared__ int sm[SCAN_B];
    int b = blockIdx.x, t = threadIdx.x;
    int i = b * SCAN_B + t;
    int v = (i < n) ? g_deg[i] : 0;
    sm[t] = v;
    __syncthreads();
    #pragma unroll
    for (int o = 1; o < SCAN_B; o <<= 1) {
        int u = (t >= o) ? sm[t - o] : 0;
        __syncthreads();
        sm[t] += u;
        __syncthreads();
    }
    if (i < n) g_off[i] = sm[t] - v;
    if (t == SCAN_B - 1) g_bsum[b] = sm[t];
}

__global__ void scan2_kernel(int nb) {
    __shared__ int sm[SCAN_B];
    int t = threadIdx.x;
    int v = (t < nb) ? g_bsum[t] : 0;
    sm[t] = v;
    __syncthreads();
    #pragma unroll
    for (int o = 1; o < SCAN_B; o <<= 1) {
        int u = (t >= o) ? sm[t - o] : 0;
        __syncthreads();
        sm[t] += u;
        __syncthreads();
    }
    if (t < nb) g_boff[t] = sm[t] - v;
}

__global__ void scan3_kernel(int n) {
    int i = blockIdx.x * blockDim.x + threadIdx.x;
    if (i < n) g_off[i] += g_boff[i / SCAN_B];
}

// scatter bumps g_off in place; afterwards g_off[d] = end of segment
__global__ void scatter_kernel(const int* __restrict__ ei, int E) {
    int e = blockIdx.x * blockDim.x + threadIdx.x;
    if (e >= E) return;
    int s = ei[e], d = ei[E + e];
    int pos = atomicAdd(&g_off[d], 1);
    g_esrc[pos] = s;
}

// ---------------- tf32 tensor-core GEMM, fp16 output ----------------
#define AS_STRIDE 20
#define BS_STRIDE 20
__global__ __launch_bounds__(256) void gemm_tf32_h(const float* __restrict__ A,
                                                   const float* __restrict__ B,
                                                   __half* __restrict__ C,
                                                   int M, int N, int K) {
    __shared__ unsigned As[128][AS_STRIDE];
    __shared__ unsigned Bs[64][BS_STRIDE];
    int t = threadIdx.x;
    int lane = t & 31, w = t >> 5;
    int wm = (w & 3) * 32;
    int wn = (w >> 2) * 32;
    int blockRow = blockIdx.y * 128;
    int blockCol = blockIdx.x * 64;

    float acc[2][4][4];
    #pragma unroll
    for (int i = 0; i < 2; i++)
        #pragma unroll
        for (int j = 0; j < 4; j++)
            #pragma unroll
            for (int q = 0; q < 4; q++) acc[i][j][q] = 0.0f;

    int aRow = t >> 1, aColBase = (t & 1) * 8;
    int gRowA = blockRow + aRow;
    int bK = t >> 4, bN = (t & 15) * 4;

    for (int k0 = 0; k0 < K; k0 += 16) {
        float4 a0v = make_float4(0.f,0.f,0.f,0.f), a1v = a0v;
        if (gRowA < M) {
            const float* ap = A + (size_t)gRowA * K + k0 + aColBase;
            a0v = *(const float4*)ap;
            a1v = *(const float4*)(ap + 4);
        }
        As[aRow][aColBase + 0] = f2tf32(a0v.x); As[aRow][aColBase + 1] = f2tf32(a0v.y);
        As[aRow][aColBase + 2] = f2tf32(a0v.z); As[aRow][aColBase + 3] = f2tf32(a0v.w);
        As[aRow][aColBase + 4] = f2tf32(a1v.x); As[aRow][aColBase + 5] = f2tf32(a1v.y);
        As[aRow][aColBase + 6] = f2tf32(a1v.z); As[aRow][aColBase + 7] = f2tf32(a1v.w);
        {
            float4 bv = *(const float4*)(B + (size_t)(k0 + bK) * N + blockCol + bN);
            Bs[bN + 0][bK] = f2tf32(bv.x);
            Bs[bN + 1][bK] = f2tf32(bv.y);
            Bs[bN + 2][bK] = f2tf32(bv.z);
            Bs[bN + 3][bK] = f2tf32(bv.w);
        }
        __syncthreads();

        int lr = lane >> 2, lc = lane & 3;
        #pragma unroll
        for (int ks = 0; ks < 2; ks++) {
            int kb = ks * 8;
            unsigned af[2][4], bf[4][2];
            #pragma unroll
            for (int ms = 0; ms < 2; ms++) {
                int mb = wm + ms * 16;
                af[ms][0] = As[mb + lr     ][kb + lc];
                af[ms][1] = As[mb + 8 + lr ][kb + lc];
                af[ms][2] = As[mb + lr     ][kb + 4 + lc];
                af[ms][3] = As[mb + 8 + lr ][kb + 4 + lc];
            }
            #pragma unroll
            for (int ns = 0; ns < 4; ns++) {
                int nb = wn + ns * 8;
                bf[ns][0] = Bs[nb + lr][kb + lc];
                bf[ns][1] = Bs[nb + lr][kb + 4 + lc];
            }
            #pragma unroll
            for (int ms = 0; ms < 2; ms++)
                #pragma unroll
                for (int ns = 0; ns < 4; ns++) {
                    asm volatile(
                        "mma.sync.aligned.m16n8k8.row.col.f32.tf32.tf32.f32 "
                        "{%0,%1,%2,%3}, {%4,%5,%6,%7}, {%8,%9}, {%0,%1,%2,%3};"
                        : "+f"(acc[ms][ns][0]), "+f"(acc[ms][ns][1]),
                          "+f"(acc[ms][ns][2]), "+f"(acc[ms][ns][3])
                        : "r"(af[ms][0]), "r"(af[ms][1]), "r"(af[ms][2]), "r"(af[ms][3]),
                          "r"(bf[ns][0]), "r"(bf[ns][1]));
                }
        }
        __syncthreads();
    }

    int lr = lane >> 2, lc = lane & 3;
    #pragma unroll
    for (int ms = 0; ms < 2; ms++) {
        int row0 = blockRow + wm + ms * 16 + lr;
        #pragma unroll
        for (int ns = 0; ns < 4; ns++) {
            int col = blockCol + wn + ns * 8 + lc * 2;
            if (row0 < M)
                *(__half2*)(C + (size_t)row0 * N + col) =
                    __floats2half2_rn(acc[ms][ns][0], acc[ms][ns][1]);
            if (row0 + 8 < M)
                *(__half2*)(C + (size_t)(row0 + 8) * N + col) =
                    __floats2half2_rn(acc[ms][ns][2], acc[ms][ns][3]);
        }
    }
}

// ---------------- attention coefficients (fp16 features) ----------------
__global__ void att_kernel_h(const __half* __restrict__ h,
                             const float* __restrict__ att_src,
                             const float* __restrict__ att_dst,
                             float* __restrict__ asrc, float* __restrict__ adst,
                             int N, int H, int C) {
    int warp = (blockIdx.x * blockDim.x + threadIdx.x) >> 5;
    int lane = threadIdx.x & 31;
    if (warp >= N * H) return;
    int hh = warp % H;
    const __half* hp = h + (size_t)warp * C;
    float ss = 0.f, sd = 0.f;
    for (int c = lane; c < C; c += 32) {
        float v = __half2float(hp[c]);
        ss += v * att_src[hh * C + c];
        sd += v * att_dst[hh * C + c];
    }
    #pragma unroll
    for (int o = 16; o; o >>= 1) {
        ss += __shfl_down_sync(0xffffffffu, ss, o);
        sd += __shfl_down_sync(0xffffffffu, sd, o);
    }
    if (lane == 0) { asrc[warp] = ss; adst[warp] = sd; }
}

// ---------------- layer1: warp per dst, 4 edge-groups x 8 lanes ----------------
// lane = grp*8 + gl; group processes edges i = grp, grp+4, ...
// lane covers head gl (32 channels). Cross-group combine via shfl_xor(8,16).
__global__ __launch_bounds__(256) void csr_agg1(const float* __restrict__ bias, int N) {
    int warp = (blockIdx.x * blockDim.x + threadIdx.x) >> 5;
    if (warp >= N) return;
    int lane = threadIdx.x & 31;
    int grp = lane >> 3, gl = lane & 7;
    int d = warp;
    int deg = g_deg[d];
    int end = g_off[d];
    int start = end - deg;
    float adst_h = g_adst1[d * 8 + gl];

    float den = 0.f;
    float acc[32];
    #pragma unroll
    for (int q = 0; q < 32; q++) acc[q] = 0.f;

#define EDGE1(IDX)                                                              \
    {                                                                           \
        int s = g_esrc[start + (IDX)];                                          \
        float ee = __expf(lrelu(g_asrc1[s * 8 + gl] + adst_h));                 \
        den += ee;                                                              \
        const __half2* hp = (const __half2*)(g_h1h + (size_t)s * H1C + gl * 32);\
        _Pragma("unroll")                                                       \
        for (int q = 0; q < 16; q++) {                                          \
            float2 v = __half22float2(hp[q]);                                   \
            acc[2 * q]     += ee * v.x;                                         \
            acc[2 * q + 1] += ee * v.y;                                         \
        }                                                                       \
    }

    int i = grp;
    for (; i + 4 < deg; i += 8) { EDGE1(i); EDGE1(i + 4); }
    if (i < deg) EDGE1(i);
#undef EDGE1

    // combine the 4 groups (xor 8 & 16 only — sums across groups, same gl)
    den += __shfl_xor_sync(0xffffffffu, den, 8);
    den += __shfl_xor_sync(0xffffffffu, den, 16);
    #pragma unroll
    for (int q = 0; q < 32; q++) {
        acc[q] += __shfl_xor_sync(0xffffffffu, acc[q], 8);
        acc[q] += __shfl_xor_sync(0xffffffffu, acc[q], 16);
    }
    float inv = 1.0f / (den + EPS_F);

    // each lane writes its group's 8-channel slice of head gl
    int cbase = gl * 32 + grp * 8;
    const float4* bp = (const float4*)(bias + cbase);
    float4 b0 = bp[0], b1 = bp[1];
    float o[8];
    o[0] = acc[grp * 8 + 0] * inv + b0.x; o[1] = acc[grp * 8 + 1] * inv + b0.y;
    o[2] = acc[grp * 8 + 2] * inv + b0.z; o[3] = acc[grp * 8 + 3] * inv + b0.w;
    o[4] = acc[grp * 8 + 4] * inv + b1.x; o[5] = acc[grp * 8 + 5] * inv + b1.y;
    o[6] = acc[grp * 8 + 6] * inv + b1.z; o[7] = acc[grp * 8 + 7] * inv + b1.w;
    #pragma unroll
    for (int q = 0; q < 8; q++) o[q] = o[q] > 0.f ? o[q] : expm1f(o[q]);
    float4* op = (float4*)(g_out1 + (size_t)d * H1C + cbase);
    op[0] = make_float4(o[0], o[1], o[2], o[3]);
    op[1] = make_float4(o[4], o[5], o[6], o[7]);
}

// ---------------- layer2: warp per dst, 4 edge-groups x 8 lanes ----------------
// lane covers channels gl*8..gl*8+7.
__global__ __launch_bounds__(256) void csr_agg2(const float* __restrict__ bias,
                                                float* __restrict__ out, int N) {
    int warp = (blockIdx.x * blockDim.x + threadIdx.x) >> 5;
    if (warp >= N) return;
    int lane = threadIdx.x & 31;
    int grp = lane >> 3, gl = lane & 7;
    int d = warp;
    int deg = g_deg[d];
    int end = g_off[d];
    int start = end - deg;
    float adst = g_adst2[d];

    float den = 0.f;
    float acc[8];
    #pragma unroll
    for (int q = 0; q < 8; q++) acc[q] = 0.f;

#define EDGE2(IDX)                                                              \
    {                                                                           \
        int s = g_esrc[start + (IDX)];                                          \
        float ee = __expf(lrelu(g_asrc2[s] + adst));                            \
        den += ee;                                                              \
        const __half2* hp = (const __half2*)(g_h2h + (size_t)s * OUT_C + gl * 8);\
        _Pragma("unroll")                                                       \
        for (int q = 0; q < 4; q++) {                                           \
            float2 v = __half22float2(hp[q]);                                   \
            acc[2 * q]     += ee * v.x;                                         \
            acc[2 * q + 1] += ee * v.y;                                         \
        }                                                                       \
    }

    int i = grp;
    for (; i + 4 < deg; i += 8) { EDGE2(i); EDGE2(i + 4); }
    if (i < deg) EDGE2(i);
#undef EDGE2

    den += __shfl_xor_sync(0xffffffffu, den, 8);
    den += __shfl_xor_sync(0xffffffffu, den, 16);
    #pragma unroll
    for (int q = 0; q < 8; q++) {
        acc[q] += __shfl_xor_sync(0xffffffffu, acc[q], 8);
        acc[q] += __shfl_xor_sync(0xffffffffu, acc[q], 16);
    }
    float inv = 1.0f / (den + EPS_F);

    // group g writes its 2-float slice (grp*2) of the lane's 8 channels
    int cbase = gl * 8 + grp * 2;
    float2 b = *(const float2*)(bias + cbase);
    float2 o = make_float2(acc[grp * 2] * inv + b.x, acc[grp * 2 + 1] * inv + b.y);
    *(float2*)(out + (size_t)d * OUT_C + cbase) = o;
}

extern "C" void kernel_launch(void* const* d_in, const int* in_sizes, int n_in,
                              void* d_out, int out_size) {
    const float* x        = (const float*)d_in[0];
    const int*   ei       = (const int*)d_in[1];
    const float* W1       = (const float*)d_in[2];
    const float* att_src1 = (const float*)d_in[3];
    const float* att_dst1 = (const float*)d_in[4];
    const float* bias1    = (const float*)d_in[5];
    const float* W2       = (const float*)d_in[6];
    const float* att_src2 = (const float*)d_in[7];
    const float* att_dst2 = (const float*)d_in[8];
    const float* bias2    = (const float*)d_in[9];
    float* out = (float*)d_out;

    const int N = in_sizes[0] / IN_C;
    const int E = in_sizes[1] / 2;
    const int NB = (N + SCAN_B - 1) / SCAN_B;

    __half *p_h1h, *p_h2h;
    float *p_out1, *p_as1, *p_ad1, *p_as2, *p_ad2;
    int *p_deg;
    cudaGetSymbolAddress((void**)&p_h1h,  g_h1h);
    cudaGetSymbolAddress((void**)&p_out1, g_out1);
    cudaGetSymbolAddress((void**)&p_h2h,  g_h2h);
    cudaGetSymbolAddress((void**)&p_as1,  g_asrc1);
    cudaGetSymbolAddress((void**)&p_ad1,  g_adst1);
    cudaGetSymbolAddress((void**)&p_as2,  g_asrc2);
    cudaGetSymbolAddress((void**)&p_ad2,  g_adst2);
    cudaGetSymbolAddress((void**)&p_deg,  g_deg);

    const int T = 256;

    // ---- CSR build ----
    ifill_kernel<<<(N + T - 1) / T, T>>>(p_deg, N, 0);
    hist_kernel<<<(E + T - 1) / T, T>>>(ei, E);
    scan1_kernel<<<NB, SCAN_B>>>(N);
    scan2_kernel<<<1, SCAN_B>>>(NB);
    scan3_kernel<<<(N + T - 1) / T, T>>>(N);
    scatter_kernel<<<(E + T - 1) / T, T>>>(ei, E);

    // ---- layer 1 ----
    {
        dim3 grid(H1C / 64, (N + 127) / 128);
        gemm_tf32_h<<<grid, 256>>>(x, W1, p_h1h, N, H1C, IN_C);
    }
    att_kernel_h<<<(N * HEADS * 32 + T - 1) / T, T>>>(p_h1h, att_src1, att_dst1,
                                                      p_as1, p_ad1, N, HEADS, HID);
    csr_agg1<<<(int)(((size_t)N * 32 + T - 1) / T), T>>>(bias1, N);

    // ---- layer 2 ----
    {
        dim3 grid(OUT_C / 64, (N + 127) / 128);
        gemm_tf32_h<<<grid, 256>>>(p_out1, W2, p_h2h, N, OUT_C, H1C);
    }
    att_kernel_h<<<(N * 32 + T - 1) / T, T>>>(p_h2h, att_src2, att_dst2,
                                              p_as2, p_ad2, N, 1, OUT_C);
    csr_agg2<<<(int)(((size_t)N * 32 + T - 1) / T), T>>>(bias2, out, N);
}

// round 10
// speedup vs baseline: 1.5953x; 1.5953x over previous
#include <cuda_runtime.h>
#include <cuda_fp16.h>
#include <math.h>

#define NN 50000
#define NE 800000
#define IN_C 128
#define HID 32
#define HEADS 8
#define H1C (HEADS*HID)   // 256
#define OUT_C 64
#define NEG_SLOPE 0.2f
#define EPS_F 1e-16f
#define SCAN_B 1024

__device__ __half g_h1h[(size_t)NN * H1C];
__device__ float  g_out1[(size_t)NN * H1C];
__device__ __half g_h2h[(size_t)NN * OUT_C];
__device__ float g_asrc1[NN * HEADS];
__device__ float g_adst1[NN * HEADS];
__device__ float g_asrc2[NN];
__device__ float g_adst2[NN];
// CSR (by dst). After scatter, g_off[d] = segment END (start = end - deg).
__device__ int g_deg[NN];
__device__ int g_off[NN];
__device__ int g_esrc[NE];
__device__ int g_bsum[(NN + SCAN_B - 1) / SCAN_B];
__device__ int g_boff[(NN + SCAN_B - 1) / SCAN_B];

__device__ __forceinline__ float lrelu(float x) { return x >= 0.0f ? x : NEG_SLOPE * x; }
__device__ __forceinline__ unsigned f2tf32(float f) {
    unsigned u;
    asm("cvt.rna.tf32.f32 %0, %1;" : "=r"(u) : "f"(f));
    return u;
}

__global__ void ifill_kernel(int* __restrict__ p, int n, int v) {
    int i = blockIdx.x * blockDim.x + threadIdx.x;
    if (i < n) p[i] = v;
}

// ---------------- CSR build ----------------
__global__ void hist_kernel(const int* __restrict__ ei, int E) {
    int e = blockIdx.x * blockDim.x + threadIdx.x;
    if (e >= E) return;
    atomicAdd(&g_deg[ei[E + e]], 1);
}

__global__ void scan1_kernel(int n) {
    __shared__ int sm[SCAN_B];
    int b = blockIdx.x, t = threadIdx.x;
    int i = b * SCAN_B + t;
    int v = (i < n) ? g_deg[i] : 0;
    sm[t] = v;
    __syncthreads();
    #pragma unroll
    for (int o = 1; o < SCAN_B; o <<= 1) {
        int u = (t >= o) ? sm[t - o] : 0;
        __syncthreads();
        sm[t] += u;
        __syncthreads();
    }
    if (i < n) g_off[i] = sm[t] - v;
    if (t == SCAN_B - 1) g_bsum[b] = sm[t];
}

__global__ void scan2_kernel(int nb) {
    __shared__ int sm[SCAN_B];
    int t = threadIdx.x;
    int v = (t < nb) ? g_bsum[t] : 0;
    sm[t] = v;
    __syncthreads();
    #pragma unroll
    for (int o = 1; o < SCAN_B; o <<= 1) {
        int u = (t >= o) ? sm[t - o] : 0;
        __syncthreads();
        sm[t] += u;
        __syncthreads();
    }
    if (t < nb) g_boff[t] = sm[t] - v;
}

__global__ void scan3_kernel(int n) {
    int i = blockIdx.x * blockDim.x + threadIdx.x;
    if (i < n) g_off[i] += g_boff[i / SCAN_B];
}

// scatter bumps g_off in place; afterwards g_off[d] = end of segment
__global__ void scatter_kernel(const int* __restrict__ ei, int E) {
    int e = blockIdx.x * blockDim.x + threadIdx.x;
    if (e >= E) return;
    int s = ei[e], d = ei[E + e];
    int pos = atomicAdd(&g_off[d], 1);
    g_esrc[pos] = s;
}

// ---------------- tf32 tensor-core GEMM, fp16 output ----------------
#define AS_STRIDE 20
#define BS_STRIDE 20
__global__ __launch_bounds__(256) void gemm_tf32_h(const float* __restrict__ A,
                                                   const float* __restrict__ B,
                                                   __half* __restrict__ C,
                                                   int M, int N, int K) {
    __shared__ unsigned As[128][AS_STRIDE];
    __shared__ unsigned Bs[64][BS_STRIDE];
    int t = threadIdx.x;
    int lane = t & 31, w = t >> 5;
    int wm = (w & 3) * 32;
    int wn = (w >> 2) * 32;
    int blockRow = blockIdx.y * 128;
    int blockCol = blockIdx.x * 64;

    float acc[2][4][4];
    #pragma unroll
    for (int i = 0; i < 2; i++)
        #pragma unroll
        for (int j = 0; j < 4; j++)
            #pragma unroll
            for (int q = 0; q < 4; q++) acc[i][j][q] = 0.0f;

    int aRow = t >> 1, aColBase = (t & 1) * 8;
    int gRowA = blockRow + aRow;
    int bK = t >> 4, bN = (t & 15) * 4;

    for (int k0 = 0; k0 < K; k0 += 16) {
        float4 a0v = make_float4(0.f,0.f,0.f,0.f), a1v = a0v;
        if (gRowA < M) {
            const float* ap = A + (size_t)gRowA * K + k0 + aColBase;
            a0v = *(const float4*)ap;
            a1v = *(const float4*)(ap + 4);
        }
        As[aRow][aColBase + 0] = f2tf32(a0v.x); As[aRow][aColBase + 1] = f2tf32(a0v.y);
        As[aRow][aColBase + 2] = f2tf32(a0v.z); As[aRow][aColBase + 3] = f2tf32(a0v.w);
        As[aRow][aColBase + 4] = f2tf32(a1v.x); As[aRow][aColBase + 5] = f2tf32(a1v.y);
        As[aRow][aColBase + 6] = f2tf32(a1v.z); As[aRow][aColBase + 7] = f2tf32(a1v.w);
        {
            float4 bv = *(const float4*)(B + (size_t)(k0 + bK) * N + blockCol + bN);
            Bs[bN + 0][bK] = f2tf32(bv.x);
            Bs[bN + 1][bK] = f2tf32(bv.y);
            Bs[bN + 2][bK] = f2tf32(bv.z);
            Bs[bN + 3][bK] = f2tf32(bv.w);
        }
        __syncthreads();

        int lr = lane >> 2, lc = lane & 3;
        #pragma unroll
        for (int ks = 0; ks < 2; ks++) {
            int kb = ks * 8;
            unsigned af[2][4], bf[4][2];
            #pragma unroll
            for (int ms = 0; ms < 2; ms++) {
                int mb = wm + ms * 16;
                af[ms][0] = As[mb + lr     ][kb + lc];
                af[ms][1] = As[mb + 8 + lr ][kb + lc];
                af[ms][2] = As[mb + lr     ][kb + 4 + lc];
                af[ms][3] = As[mb + 8 + lr ][kb + 4 + lc];
            }
            #pragma unroll
            for (int ns = 0; ns < 4; ns++) {
                int nb = wn + ns * 8;
                bf[ns][0] = Bs[nb + lr][kb + lc];
                bf[ns][1] = Bs[nb + lr][kb + 4 + lc];
            }
            #pragma unroll
            for (int ms = 0; ms < 2; ms++)
                #pragma unroll
                for (int ns = 0; ns < 4; ns++) {
                    asm volatile(
                        "mma.sync.aligned.m16n8k8.row.col.f32.tf32.tf32.f32 "
                        "{%0,%1,%2,%3}, {%4,%5,%6,%7}, {%8,%9}, {%0,%1,%2,%3};"
                        : "+f"(acc[ms][ns][0]), "+f"(acc[ms][ns][1]),
                          "+f"(acc[ms][ns][2]), "+f"(acc[ms][ns][3])
                        : "r"(af[ms][0]), "r"(af[ms][1]), "r"(af[ms][2]), "r"(af[ms][3]),
                          "r"(bf[ns][0]), "r"(bf[ns][1]));
                }
        }
        __syncthreads();
    }

    int lr = lane >> 2, lc = lane & 3;
    #pragma unroll
    for (int ms = 0; ms < 2; ms++) {
        int row0 = blockRow + wm + ms * 16 + lr;
        #pragma unroll
        for (int ns = 0; ns < 4; ns++) {
            int col = blockCol + wn + ns * 8 + lc * 2;
            if (row0 < M)
                *(__half2*)(C + (size_t)row0 * N + col) =
                    __floats2half2_rn(acc[ms][ns][0], acc[ms][ns][1]);
            if (row0 + 8 < M)
                *(__half2*)(C + (size_t)(row0 + 8) * N + col) =
                    __floats2half2_rn(acc[ms][ns][2], acc[ms][ns][3]);
        }
    }
}

// ---------------- attention coefficients (fp16 features) ----------------
__global__ void att_kernel_h(const __half* __restrict__ h,
                             const float* __restrict__ att_src,
                             const float* __restrict__ att_dst,
                             float* __restrict__ asrc, float* __restrict__ adst,
                             int N, int H, int C) {
    int warp = (blockIdx.x * blockDim.x + threadIdx.x) >> 5;
    int lane = threadIdx.x & 31;
    if (warp >= N * H) return;
    int hh = warp % H;
    const __half* hp = h + (size_t)warp * C;
    float ss = 0.f, sd = 0.f;
    for (int c = lane; c < C; c += 32) {
        float v = __half2float(hp[c]);
        ss += v * att_src[hh * C + c];
        sd += v * att_dst[hh * C + c];
    }
    #pragma unroll
    for (int o = 16; o; o >>= 1) {
        ss += __shfl_down_sync(0xffffffffu, ss, o);
        sd += __shfl_down_sync(0xffffffffu, sd, o);
    }
    if (lane == 0) { asrc[warp] = ss; adst[warp] = sd; }
}

// ---------------- layer1: warp per dst node, single pass, 4x edge unroll ----------------
__global__ __launch_bounds__(256) void csr_agg1(const float* __restrict__ bias, int N) {
    int warp = (blockIdx.x * blockDim.x + threadIdx.x) >> 5;
    if (warp >= N) return;
    int lane = threadIdx.x & 31;
    int d = warp;
    int deg = g_deg[d];
    int end = g_off[d];
    int start = end - deg;
    int h = lane >> 2;
    float adst_h = g_adst1[d * 8 + h];

    float den = 0.f;
    float acc[8];
    #pragma unroll
    for (int q = 0; q < 8; q++) acc[q] = 0.f;

    for (int base = 0; base < deg; base += 32) {
        int cnt = min(32, deg - base);
        int s_reg = (base + lane < deg) ? g_esrc[start + base + lane] : 0;
        int j = 0;
        for (; j + 4 <= cnt; j += 4) {
            int s0 = __shfl_sync(0xffffffffu, s_reg, j);
            int s1 = __shfl_sync(0xffffffffu, s_reg, j + 1);
            int s2 = __shfl_sync(0xffffffffu, s_reg, j + 2);
            int s3 = __shfl_sync(0xffffffffu, s_reg, j + 3);
            // 4 independent score loads
            float a0 = g_asrc1[s0 * 8 + h];
            float a1 = g_asrc1[s1 * 8 + h];
            float a2 = g_asrc1[s2 * 8 + h];
            float a3 = g_asrc1[s3 * 8 + h];
            // 4 independent 16B feature loads
            const float4* p0 = (const float4*)(g_h1h + (size_t)s0 * H1C + lane * 8);
            const float4* p1 = (const float4*)(g_h1h + (size_t)s1 * H1C + lane * 8);
            const float4* p2 = (const float4*)(g_h1h + (size_t)s2 * H1C + lane * 8);
            const float4* p3 = (const float4*)(g_h1h + (size_t)s3 * H1C + lane * 8);
            float4 r0 = p0[0], r1 = p1[0], r2 = p2[0], r3 = p3[0];
            float e0 = __expf(lrelu(a0 + adst_h));
            float e1 = __expf(lrelu(a1 + adst_h));
            float e2 = __expf(lrelu(a2 + adst_h));
            float e3 = __expf(lrelu(a3 + adst_h));
            den += (e0 + e1) + (e2 + e3);
            const __half2* q0 = (const __half2*)&r0;
            const __half2* q1 = (const __half2*)&r1;
            const __half2* q2 = (const __half2*)&r2;
            const __half2* q3 = (const __half2*)&r3;
            #pragma unroll
            for (int q = 0; q < 4; q++) {
                float2 v0 = __half22float2(q0[q]);
                float2 v1 = __half22float2(q1[q]);
                float2 v2 = __half22float2(q2[q]);
                float2 v3 = __half22float2(q3[q]);
                acc[2*q]   += e0 * v0.x + e1 * v1.x + e2 * v2.x + e3 * v3.x;
                acc[2*q+1] += e0 * v0.y + e1 * v1.y + e2 * v2.y + e3 * v3.y;
            }
        }
        for (; j < cnt; j++) {
            int s = __shfl_sync(0xffffffffu, s_reg, j);
            float ee = __expf(lrelu(g_asrc1[s * 8 + h] + adst_h));
            den += ee;
            const __half2* hp = (const __half2*)(g_h1h + (size_t)s * H1C + lane * 8);
            #pragma unroll
            for (int q = 0; q < 4; q++) {
                float2 v = __half22float2(hp[q]);
                acc[2*q]   += ee * v.x;
                acc[2*q+1] += ee * v.y;
            }
        }
    }
    float inv = 1.0f / (den + EPS_F);
    const float4* bp = (const float4*)(bias + lane * 8);
    float4 b0 = bp[0], b1 = bp[1];
    float o[8];
    o[0] = acc[0] * inv + b0.x; o[1] = acc[1] * inv + b0.y;
    o[2] = acc[2] * inv + b0.z; o[3] = acc[3] * inv + b0.w;
    o[4] = acc[4] * inv + b1.x; o[5] = acc[5] * inv + b1.y;
    o[6] = acc[6] * inv + b1.z; o[7] = acc[7] * inv + b1.w;
    #pragma unroll
    for (int q = 0; q < 8; q++) o[q] = o[q] > 0.f ? o[q] : expm1f(o[q]);
    float4* op = (float4*)(g_out1 + (size_t)d * H1C + lane * 8);
    op[0] = make_float4(o[0], o[1], o[2], o[3]);
    op[1] = make_float4(o[4], o[5], o[6], o[7]);
}

// ---------------- layer2: warp per dst node, single pass, 4x edge unroll ----------------
__global__ __launch_bounds__(256) void csr_agg2(const float* __restrict__ bias,
                                                float* __restrict__ out, int N) {
    int warp = (blockIdx.x * blockDim.x + threadIdx.x) >> 5;
    if (warp >= N) return;
    int lane = threadIdx.x & 31;
    int d = warp;
    int deg = g_deg[d];
    int end = g_off[d];
    int start = end - deg;
    float adst = g_adst2[d];

    float den = 0.f;
    float accx = 0.f, accy = 0.f;
    for (int base = 0; base < deg; base += 32) {
        int cnt = min(32, deg - base);
        int s_reg = (base + lane < deg) ? g_esrc[start + base + lane] : 0;
        int j = 0;
        for (; j + 4 <= cnt; j += 4) {
            int s0 = __shfl_sync(0xffffffffu, s_reg, j);
            int s1 = __shfl_sync(0xffffffffu, s_reg, j + 1);
            int s2 = __shfl_sync(0xffffffffu, s_reg, j + 2);
            int s3 = __shfl_sync(0xffffffffu, s_reg, j + 3);
            float a0 = g_asrc2[s0];
            float a1 = g_asrc2[s1];
            float a2 = g_asrc2[s2];
            float a3 = g_asrc2[s3];
            __half2 w0 = *(const __half2*)(g_h2h + (size_t)s0 * OUT_C + lane * 2);
            __half2 w1 = *(const __half2*)(g_h2h + (size_t)s1 * OUT_C + lane * 2);
            __half2 w2 = *(const __half2*)(g_h2h + (size_t)s2 * OUT_C + lane * 2);
            __half2 w3 = *(const __half2*)(g_h2h + (size_t)s3 * OUT_C + lane * 2);
            float e0 = __expf(lrelu(a0 + adst));
            float e1 = __expf(lrelu(a1 + adst));
            float e2 = __expf(lrelu(a2 + adst));
            float e3 = __expf(lrelu(a3 + adst));
            den += (e0 + e1) + (e2 + e3);
            float2 v0 = __half22float2(w0);
            float2 v1 = __half22float2(w1);
            float2 v2 = __half22float2(w2);
            float2 v3 = __half22float2(w3);
            accx += e0 * v0.x + e1 * v1.x + e2 * v2.x + e3 * v3.x;
            accy += e0 * v0.y + e1 * v1.y + e2 * v2.y + e3 * v3.y;
        }
        for (; j < cnt; j++) {
            int s = __shfl_sync(0xffffffffu, s_reg, j);
            float ee = __expf(lrelu(g_asrc2[s] + adst));
            den += ee;
            float2 v = __half22float2(*(const __half2*)(g_h2h + (size_t)s * OUT_C + lane * 2));
            accx += ee * v.x; accy += ee * v.y;
        }
    }
    float inv = 1.0f / (den + EPS_F);
    float2 b = *(const float2*)(bias + lane * 2);
    *(float2*)(out + (size_t)d * OUT_C + lane * 2) =
        make_float2(accx * inv + b.x, accy * inv + b.y);
}

extern "C" void kernel_launch(void* const* d_in, const int* in_sizes, int n_in,
                              void* d_out, int out_size) {
    const float* x        = (const float*)d_in[0];
    const int*   ei       = (const int*)d_in[1];
    const float* W1       = (const float*)d_in[2];
    const float* att_src1 = (const float*)d_in[3];
    const float* att_dst1 = (const float*)d_in[4];
    const float* bias1    = (const float*)d_in[5];
    const float* W2       = (const float*)d_in[6];
    const float* att_src2 = (const float*)d_in[7];
    const float* att_dst2 = (const float*)d_in[8];
    const float* bias2    = (const float*)d_in[9];
    float* out = (float*)d_out;

    const int N = in_sizes[0] / IN_C;
    const int E = in_sizes[1] / 2;
    const int NB = (N + SCAN_B - 1) / SCAN_B;

    __half *p_h1h, *p_h2h;
    float *p_out1, *p_as1, *p_ad1, *p_as2, *p_ad2;
    int *p_deg;
    cudaGetSymbolAddress((void**)&p_h1h,  g_h1h);
    cudaGetSymbolAddress((void**)&p_out1, g_out1);
    cudaGetSymbolAddress((void**)&p_h2h,  g_h2h);
    cudaGetSymbolAddress((void**)&p_as1,  g_asrc1);
    cudaGetSymbolAddress((void**)&p_ad1,  g_adst1);
    cudaGetSymbolAddress((void**)&p_as2,  g_asrc2);
    cudaGetSymbolAddress((void**)&p_ad2,  g_adst2);
    cudaGetSymbolAddress((void**)&p_deg,  g_deg);

    const int T = 256;

    // ---- CSR build ----
    ifill_kernel<<<(N + T - 1) / T, T>>>(p_deg, N, 0);
    hist_kernel<<<(E + T - 1) / T, T>>>(ei, E);
    scan1_kernel<<<NB, SCAN_B>>>(N);
    scan2_kernel<<<1, SCAN_B>>>(NB);
    scan3_kernel<<<(N + T - 1) / T, T>>>(N);
    scatter_kernel<<<(E + T - 1) / T, T>>>(ei, E);

    // ---- layer 1 ----
    {
        dim3 grid(H1C / 64, (N + 127) / 128);
        gemm_tf32_h<<<grid, 256>>>(x, W1, p_h1h, N, H1C, IN_C);
    }
    att_kernel_h<<<(N * HEADS * 32 + T - 1) / T, T>>>(p_h1h, att_src1, att_dst1,
                                                      p_as1, p_ad1, N, HEADS, HID);
    csr_agg1<<<(int)(((size_t)N * 32 + T - 1) / T), T>>>(bias1, N);

    // ---- layer 2 ----
    {
        dim3 grid(OUT_C / 64, (N + 127) / 128);
        gemm_tf32_h<<<grid, 256>>>(p_out1, W2, p_h2h, N, OUT_C, H1C);
    }
    att_kernel_h<<<(N * 32 + T - 1) / T, T>>>(p_h2h, att_src2, att_dst2,
                                              p_as2, p_ad2, N, 1, OUT_C);
    csr_agg2<<<(int)(((size_t)N * 32 + T - 1) / T), T>>>(bias2, out, N);
}